// round 1
// baseline (speedup 1.0000x reference)
#include <cuda_runtime.h>
#include <math.h>

#define NFRAMES 480          // B(16) * STEPS(30)
#define KDIM    5625         // 75*75 pooled cells
#define NNEUR   54
#define NPAD    64
#define STEPS   30
#define BATCH   16
#define BK      75           // K-chunk for split-K GEMM
#define NCHUNK  (KDIM / BK)  // 75
#define BM      48           // frames per GEMM block

// -------- scratch (device globals; no allocation allowed) --------
__device__ float g_xp[NFRAMES * KDIM];            // pooled frames [480][5625]  ~10.8 MB
__device__ float g_wT[KDIM * NPAD];               // transposed padded weights  ~1.44 MB
__device__ float g_partial[NCHUNK * NFRAMES * NNEUR]; // split-K partials       ~7.8 MB
__device__ float g_frames[NFRAMES * NNEUR];       // merged FC outputs

// ================= 1) avg-pool 8x8 : x[480][600][600] -> xp[480][5625] =================
__global__ void pool_kernel(const float* __restrict__ x) {
    int i = blockIdx.x * blockDim.x + threadIdx.x;
    if (i >= NFRAMES * KDIM) return;
    int f  = i / KDIM;
    int k  = i - f * KDIM;
    int pr = k / 75;
    int pc = k - pr * 75;
    const float* p = x + ((size_t)f * 600 + (size_t)pr * 8) * 600 + pc * 8;
    float s = 0.f;
#pragma unroll
    for (int r = 0; r < 8; r++) {
        float4 a = *(const float4*)(p + (size_t)r * 600);
        float4 b = *(const float4*)(p + (size_t)r * 600 + 4);
        s += ((a.x + a.y) + (a.z + a.w)) + ((b.x + b.y) + (b.z + b.w));
    }
    g_xp[i] = s * (1.f / 64.f);
}

// ================= 2) transpose weights: fc_w[54][5625] -> wT[5625][64] (zero-pad) =====
__global__ void wT_kernel(const float* __restrict__ fc_w) {
    int i = blockIdx.x * blockDim.x + threadIdx.x;
    if (i >= KDIM * NPAD) return;
    int k = i >> 6;
    int n = i & 63;
    g_wT[i] = (n < NNEUR) ? fc_w[n * KDIM + k] : 0.f;
}

// ================= 3) split-K GEMM: partial[chunk][f][n] = xp[f,kchunk] . w[n,kchunk] ===
// grid (10, 75), 192 threads. smem: xs[48][76] + ws[75][64] = 33.8 KB.
__global__ void gemm_kernel() {
    __shared__ float xs[BM * (BK + 1)];
    __shared__ float ws[BK * NPAD];
    int m0 = blockIdx.x * BM;
    int k0 = blockIdx.y * BK;
    int tid = threadIdx.x;

    for (int idx = tid; idx < BM * BK; idx += 192) {
        int f = idx / BK, k = idx - f * BK;
        xs[f * (BK + 1) + k] = g_xp[(size_t)(m0 + f) * KDIM + k0 + k];
    }
    for (int idx = tid; idx < BK * NPAD; idx += 192) {
        // idx = k*64 + n ; coalesced load from g_wT, coalesced store to ws
        ws[idx] = g_wT[(size_t)k0 * NPAD + idx];
    }
    __syncthreads();

    int tx = tid & 15;   // n-tile: 4 neurons
    int ty = tid >> 4;   // f-tile: 4 frames (ty 0..11)
    float acc[4][4] = {};
#pragma unroll 5
    for (int k = 0; k < BK; k++) {
        float4 wv = *(const float4*)&ws[k * NPAD + tx * 4];
        float a0 = xs[(ty * 4 + 0) * (BK + 1) + k];
        float a1 = xs[(ty * 4 + 1) * (BK + 1) + k];
        float a2 = xs[(ty * 4 + 2) * (BK + 1) + k];
        float a3 = xs[(ty * 4 + 3) * (BK + 1) + k];
        acc[0][0] += a0 * wv.x; acc[0][1] += a0 * wv.y; acc[0][2] += a0 * wv.z; acc[0][3] += a0 * wv.w;
        acc[1][0] += a1 * wv.x; acc[1][1] += a1 * wv.y; acc[1][2] += a1 * wv.z; acc[1][3] += a1 * wv.w;
        acc[2][0] += a2 * wv.x; acc[2][1] += a2 * wv.y; acc[2][2] += a2 * wv.z; acc[2][3] += a2 * wv.w;
        acc[3][0] += a3 * wv.x; acc[3][1] += a3 * wv.y; acc[3][2] += a3 * wv.z; acc[3][3] += a3 * wv.w;
    }
    int ch = blockIdx.y;
#pragma unroll
    for (int r = 0; r < 4; r++) {
        int f = m0 + ty * 4 + r;
#pragma unroll
        for (int c = 0; c < 4; c++) {
            int n = tx * 4 + c;
            if (n < NNEUR)
                g_partial[(size_t)ch * (NFRAMES * NNEUR) + f * NNEUR + n] = acc[r][c];
        }
    }
}

// ================= 4) merge partials + bias (fixed order => deterministic) =============
__global__ void merge_kernel(const float* __restrict__ fc_b) {
    int i = blockIdx.x * blockDim.x + threadIdx.x;
    if (i >= NFRAMES * NNEUR) return;
    int n = i % NNEUR;
    float s = fc_b[n];
#pragma unroll 15
    for (int c = 0; c < NCHUNK; c++)
        s += g_partial[(size_t)c * (NFRAMES * NNEUR) + i];
    g_frames[i] = s;
}

// ================= 5) sequential spike scan, single block of 864 threads ===============
__global__ void scan_kernel(const float* __restrict__ lw, const float* __restrict__ hw,
                            float* __restrict__ out) {
    __shared__ float hs[BATCH * NNEUR];   // per-(b,n) weighted hist sums
    __shared__ float bsum[BATCH];
    __shared__ float wsum[27];
    __shared__ float thr_s;

    int tid  = threadIdx.x;               // 0..863 (27 full warps)
    int b    = tid / NNEUR;
    int n    = tid - b * NNEUR;
    int wid  = tid >> 5;
    int lane = tid & 31;

    float w0 = hw[0], w1 = hw[1], w2 = hw[2], w3 = hw[3];
    float l0 = lw[n * 4 + 0], l1 = lw[n * 4 + 1], l2 = lw[n * 4 + 2], l3 = lw[n * 4 + 3];
    float h0 = 0.f, h1 = 0.f, h2 = 0.f, h3 = 0.f, count = 0.f;

    for (int t = 0; t < STEPS; t++) {
        float frame = g_frames[(b * STEPS + t) * NNEUR + n];  // issue early, L2 hit
        float hsum = h0 * l0 + h1 * l1 + h2 * l2 + h3 * l3;
        float hh   = h0 * w0 + h1 * w1 + h2 * w2 + h3 * w3;
        hs[tid] = hsum;
        __syncthreads();

        // per-batch lateral sums: warp w handles batch w (16 of 27 warps)
        if (wid < BATCH) {
            float v = hs[wid * NNEUR + lane];
            if (lane < NNEUR - 32) v += hs[wid * NNEUR + 32 + lane];
            v += __shfl_xor_sync(0xffffffffu, v, 16);
            v += __shfl_xor_sync(0xffffffffu, v, 8);
            v += __shfl_xor_sync(0xffffffffu, v, 4);
            v += __shfl_xor_sync(0xffffffffu, v, 2);
            v += __shfl_xor_sync(0xffffffffu, v, 1);
            if (lane == 0) bsum[wid] = v;
        }
        __syncthreads();

        float cur  = frame + (bsum[b] - hsum) + hh;
        float rate = expf(cur);

        // global mean of rate over all 864
        float rs = rate;
        rs += __shfl_xor_sync(0xffffffffu, rs, 16);
        rs += __shfl_xor_sync(0xffffffffu, rs, 8);
        rs += __shfl_xor_sync(0xffffffffu, rs, 4);
        rs += __shfl_xor_sync(0xffffffffu, rs, 2);
        rs += __shfl_xor_sync(0xffffffffu, rs, 1);
        if (lane == 0) wsum[wid] = rs;
        __syncthreads();
        if (wid == 0) {
            float v = (lane < 27) ? wsum[lane] : 0.f;
            v += __shfl_xor_sync(0xffffffffu, v, 16);
            v += __shfl_xor_sync(0xffffffffu, v, 8);
            v += __shfl_xor_sync(0xffffffffu, v, 4);
            v += __shfl_xor_sync(0xffffffffu, v, 2);
            v += __shfl_xor_sync(0xffffffffu, v, 1);
            if (lane == 0) thr_s = v * (1.f / 864.f);
        }
        __syncthreads();

        float s = (rate > thr_s) ? 1.f : 0.f;
        count += s;
        h0 = h1; h1 = h2; h2 = h3; h3 = s;
    }
    // softplus(count), count >= 0 so the stable form is exact
    out[tid] = count + log1pf(expf(-count));
}

// =======================================================================================
extern "C" void kernel_launch(void* const* d_in, const int* in_sizes, int n_in,
                              void* d_out, int out_size) {
    const float* x    = (const float*)d_in[0];
    const float* fc_w = (const float*)d_in[1];
    const float* fc_b = (const float*)d_in[2];
    const float* lw   = (const float*)d_in[3];
    const float* hw   = (const float*)d_in[4];
    float* out = (float*)d_out;

    int npool = NFRAMES * KDIM;                         // 2,700,000
    pool_kernel<<<(npool + 255) / 256, 256>>>(x);
    wT_kernel<<<(KDIM * NPAD + 255) / 256, 256>>>(fc_w);
    gemm_kernel<<<dim3(NFRAMES / BM, NCHUNK), 192>>>();
    merge_kernel<<<(NFRAMES * NNEUR + 255) / 256, 256>>>(fc_b);
    scan_kernel<<<1, BATCH * NNEUR>>>(lw, hw, out);
    (void)in_sizes; (void)n_in; (void)out_size;
}

// round 2
// speedup vs baseline: 1.0098x; 1.0098x over previous
#include <cuda_runtime.h>
#include <math.h>

#define NFRAMES 480          // B(16) * STEPS(30)
#define KDIM    5625         // 75*75 pooled cells
#define NNEUR   54
#define NPAD    64
#define STEPS   30
#define BATCH   16
#define FT      8            // frames per fused block
#define CROWS   5            // pooled rows per chunk
#define CCELLS  (CROWS * 75) // 375 cells per chunk
#define NCHUNK  15           // 75 / CROWS

// -------- scratch (device globals; no allocation allowed) --------
__device__ float g_wT[KDIM * NPAD];                     // transposed padded weights ~1.44 MB
__device__ float g_partial[NCHUNK * NFRAMES * NNEUR];   // split-K partials
__device__ float g_frames[NFRAMES * NNEUR];             // merged FC outputs

// ================= 1) transpose weights: fc_w[54][5625] -> wT[5625][64] (zero-pad) =====
__global__ void wT_kernel(const float* __restrict__ fc_w) {
    int i = blockIdx.x * blockDim.x + threadIdx.x;
    if (i >= KDIM * NPAD) return;
    int k = i >> 6;
    int n = i & 63;
    g_wT[i] = (n < NNEUR) ? fc_w[n * KDIM + k] : 0.f;
}

// ================= 2) fused pool(8x8 avg) + FC, split-K over pooled-row chunks =========
// grid (NFRAMES/FT = 60, NCHUNK = 15), 256 threads.
// Block: pools FT frames x 375 cells into smem, then dots against wT tile (read once
// per block from L2 for all FT frames), reduces 4 k-groups in fixed order.
__global__ void fused_kernel(const float* __restrict__ x) {
    __shared__ float xp_s[FT * CCELLS];        // 12000 B
    __shared__ float red[4 * FT * NPAD];       //  8192 B

    const int tid = threadIdx.x;
    const int f0  = blockIdx.x * FT;
    const int pr0 = blockIdx.y * CROWS;
    const int k0  = blockIdx.y * CCELLS;       // global pooled-cell base

    // ---- stage 1: pooling. each iteration computes one pooled cell (64 input floats)
    for (int idx = tid; idx < FT * CCELLS; idx += 256) {
        int f  = idx / CCELLS;
        int c  = idx - f * CCELLS;
        int pr = c / 75;
        int pc = c - pr * 75;
        const float* p = x + ((size_t)(f0 + f) * 600 + (size_t)(pr0 + pr) * 8) * 600 + pc * 8;
        float s = 0.f;
#pragma unroll
        for (int r = 0; r < 8; r++) {
            float4 a = *(const float4*)(p + (size_t)r * 600);
            float4 b = *(const float4*)(p + (size_t)r * 600 + 4);
            s += ((a.x + a.y) + (a.z + a.w)) + ((b.x + b.y) + (b.z + b.w));
        }
        xp_s[idx] = s * (1.f / 64.f);
    }
    __syncthreads();

    // ---- stage 2: FC. n = tid&63, k-group g = tid>>6 (4 groups over the 375 cells)
    const int n = tid & 63;
    const int g = tid >> 6;
    float acc[FT];
#pragma unroll
    for (int f = 0; f < FT; f++) acc[f] = 0.f;

    for (int p = g; p < CCELLS; p += 4) {
        float w = g_wT[(size_t)(k0 + p) * NPAD + n];   // warp-coalesced 128B, L2-resident
#pragma unroll
        for (int f = 0; f < FT; f++)
            acc[f] += xp_s[f * CCELLS + p] * w;        // smem broadcast across n
    }
#pragma unroll
    for (int f = 0; f < FT; f++)
        red[(g * FT + f) * NPAD + n] = acc[f];
    __syncthreads();

    // ---- stage 3: fixed-order reduction over 4 k-groups, write split-K partial
    for (int idx = tid; idx < FT * NPAD; idx += 256) {
        int f = idx >> 6;
        int nn = idx & 63;
        float s = ((red[(0 * FT + f) * NPAD + nn]  + red[(1 * FT + f) * NPAD + nn])
                +  (red[(2 * FT + f) * NPAD + nn]  + red[(3 * FT + f) * NPAD + nn]));
        if (nn < NNEUR)
            g_partial[((size_t)blockIdx.y * NFRAMES + (f0 + f)) * NNEUR + nn] = s;
    }
}

// ================= 3) merge partials + bias (fixed order => deterministic) =============
__global__ void merge_kernel(const float* __restrict__ fc_b) {
    int i = blockIdx.x * blockDim.x + threadIdx.x;
    if (i >= NFRAMES * NNEUR) return;
    int n = i % NNEUR;
    float s = fc_b[n];
#pragma unroll
    for (int c = 0; c < NCHUNK; c++)
        s += g_partial[(size_t)c * (NFRAMES * NNEUR) + i];
    g_frames[i] = s;
}

// ================= 4) sequential spike scan, single block of 864 threads ===============
__global__ void scan_kernel(const float* __restrict__ lw, const float* __restrict__ hw,
                            float* __restrict__ out) {
    __shared__ float hs[BATCH * NNEUR];   // per-(b,n) weighted hist sums
    __shared__ float bsum[BATCH];
    __shared__ float wsum[27];
    __shared__ float thr_s;

    int tid  = threadIdx.x;               // 0..863 (27 full warps)
    int b    = tid / NNEUR;
    int n    = tid - b * NNEUR;
    int wid  = tid >> 5;
    int lane = tid & 31;

    float w0 = hw[0], w1 = hw[1], w2 = hw[2], w3 = hw[3];
    float l0 = lw[n * 4 + 0], l1 = lw[n * 4 + 1], l2 = lw[n * 4 + 2], l3 = lw[n * 4 + 3];
    float h0 = 0.f, h1 = 0.f, h2 = 0.f, h3 = 0.f, count = 0.f;

    for (int t = 0; t < STEPS; t++) {
        float frame = g_frames[(b * STEPS + t) * NNEUR + n];  // issue early, L2 hit
        float hsum = h0 * l0 + h1 * l1 + h2 * l2 + h3 * l3;
        float hh   = h0 * w0 + h1 * w1 + h2 * w2 + h3 * w3;
        hs[tid] = hsum;
        __syncthreads();

        // per-batch lateral sums: warp w handles batch w (16 of 27 warps)
        if (wid < BATCH) {
            float v = hs[wid * NNEUR + lane];
            if (lane < NNEUR - 32) v += hs[wid * NNEUR + 32 + lane];
            v += __shfl_xor_sync(0xffffffffu, v, 16);
            v += __shfl_xor_sync(0xffffffffu, v, 8);
            v += __shfl_xor_sync(0xffffffffu, v, 4);
            v += __shfl_xor_sync(0xffffffffu, v, 2);
            v += __shfl_xor_sync(0xffffffffu, v, 1);
            if (lane == 0) bsum[wid] = v;
        }
        __syncthreads();

        float cur  = frame + (bsum[b] - hsum) + hh;
        float rate = expf(cur);

        // global mean of rate over all 864
        float rs = rate;
        rs += __shfl_xor_sync(0xffffffffu, rs, 16);
        rs += __shfl_xor_sync(0xffffffffu, rs, 8);
        rs += __shfl_xor_sync(0xffffffffu, rs, 4);
        rs += __shfl_xor_sync(0xffffffffu, rs, 2);
        rs += __shfl_xor_sync(0xffffffffu, rs, 1);
        if (lane == 0) wsum[wid] = rs;
        __syncthreads();
        if (wid == 0) {
            float v = (lane < 27) ? wsum[lane] : 0.f;
            v += __shfl_xor_sync(0xffffffffu, v, 16);
            v += __shfl_xor_sync(0xffffffffu, v, 8);
            v += __shfl_xor_sync(0xffffffffu, v, 4);
            v += __shfl_xor_sync(0xffffffffu, v, 2);
            v += __shfl_xor_sync(0xffffffffu, v, 1);
            if (lane == 0) thr_s = v * (1.f / 864.f);
        }
        __syncthreads();

        float s = (rate > thr_s) ? 1.f : 0.f;
        count += s;
        h0 = h1; h1 = h2; h2 = h3; h3 = s;
    }
    // softplus(count), count >= 0 so the stable form is exact
    out[tid] = count + log1pf(expf(-count));
}

// =======================================================================================
extern "C" void kernel_launch(void* const* d_in, const int* in_sizes, int n_in,
                              void* d_out, int out_size) {
    const float* x    = (const float*)d_in[0];
    const float* fc_w = (const float*)d_in[1];
    const float* fc_b = (const float*)d_in[2];
    const float* lw   = (const float*)d_in[3];
    const float* hw   = (const float*)d_in[4];
    float* out = (float*)d_out;

    wT_kernel<<<(KDIM * NPAD + 255) / 256, 256>>>(fc_w);
    fused_kernel<<<dim3(NFRAMES / FT, NCHUNK), 256>>>(x);
    merge_kernel<<<(NFRAMES * NNEUR + 255) / 256, 256>>>(fc_b);
    scan_kernel<<<1, BATCH * NNEUR>>>(lw, hw, out);
    (void)in_sizes; (void)n_in; (void)out_size;
}